// round 1
// baseline (speedup 1.0000x reference)
#include <cuda_runtime.h>
#include <cuda_bf16.h>

// Problem constants (fixed shapes from reference)
#define N_NODES 32768      // B*S = 64*512
#define IN_F    256
#define OUT_F   256
#define NBASES  3
#define N_EDGES 262144
#define TCOLS   768        // NBASES * OUT_F, t layout [n][b][o]

// Scratch: t = h @ bases, [N_NODES][TCOLS] = 96 MB static device array
__device__ float g_t[(size_t)N_NODES * TCOLS];

// ---------------------------------------------------------------------------
// Fused GEMM: C[n, b*256+o] = sum_i h[n,i] * bases[b,i,o]
// A = text [32768, 256], "B" = bases viewed as [256, 768] (per-64-col tile the
// basis index b is constant since 256 % 64 == 0).
// Tile 64x64x16, 256 threads, 4x4 microtile per thread. fp32.
// ---------------------------------------------------------------------------
#define BM 64
#define BN 64
#define BK 16

__global__ void __launch_bounds__(256) gemm_bases_kernel(
    const float* __restrict__ A, const float* __restrict__ bases)
{
    __shared__ float As[BK][BM + 4];   // +4 pad: keeps float4 reads aligned, kills store conflicts
    __shared__ float Bs[BK][BN];

    const int col0 = blockIdx.x * BN;
    const int row0 = blockIdx.y * BM;
    const int b    = col0 >> 8;                       // basis index for this tile
    const float* Bbase = bases + (size_t)b * (IN_F * OUT_F) + (col0 - (b << 8));

    const int tid = threadIdx.x;
    const int tx = tid & 15;          // output-col group
    const int ty = tid >> 4;          // output-row group
    const int ar = tid >> 2, aq = tid & 3;    // A-tile load: row, k-quad
    const int bi = tid >> 4, bq = tid & 15;   // B-tile load: k-row, col-quad

    float acc[4][4] = {};

    for (int k0 = 0; k0 < IN_F; k0 += BK) {
        // Load A tile (64 rows x 16 k) -> As[k][row]
        float4 va = *(const float4*)(A + (size_t)(row0 + ar) * IN_F + k0 + aq * 4);
        As[aq * 4 + 0][ar] = va.x;
        As[aq * 4 + 1][ar] = va.y;
        As[aq * 4 + 2][ar] = va.z;
        As[aq * 4 + 3][ar] = va.w;
        // Load B tile (16 k x 64 cols)
        float4 vb = *(const float4*)(Bbase + (size_t)(k0 + bi) * OUT_F + bq * 4);
        *(float4*)&Bs[bi][bq * 4] = vb;
        __syncthreads();

        #pragma unroll
        for (int k = 0; k < BK; k++) {
            float4 av = *(const float4*)&As[k][ty * 4];
            float4 bv = *(const float4*)&Bs[k][tx * 4];
            float a4[4] = {av.x, av.y, av.z, av.w};
            float b4[4] = {bv.x, bv.y, bv.z, bv.w};
            #pragma unroll
            for (int i = 0; i < 4; i++)
                #pragma unroll
                for (int j = 0; j < 4; j++)
                    acc[i][j] = fmaf(a4[i], b4[j], acc[i][j]);
        }
        __syncthreads();
    }

    #pragma unroll
    for (int i = 0; i < 4; i++) {
        int row = row0 + ty * 4 + i;
        float4 v = make_float4(acc[i][0], acc[i][1], acc[i][2], acc[i][3]);
        *(float4*)(g_t + (size_t)row * TCOLS + col0 + tx * 4) = v;
    }
}

// ---------------------------------------------------------------------------
// Init output with bias (d_out is poisoned to 0xAA; also the agg accumulator)
// ---------------------------------------------------------------------------
__global__ void init_out_kernel(float* __restrict__ out, const float* __restrict__ bias)
{
    int i = blockIdx.x * blockDim.x + threadIdx.x;   // over N_NODES*OUT_F/4 float4s
    if (i >= N_NODES * OUT_F / 4) return;
    float4 bv = *(const float4*)(bias + ((i & 63) << 2));  // o = (i*4) % 256
    ((float4*)out)[i] = bv;
}

// ---------------------------------------------------------------------------
// Edge kernel: msg_e = sum_b comp[rel_e,b] * t[src_e, b, :], scatter-add to
// out[dst_e]. 64 threads per edge (one float4 of the 256 outputs per thread),
// 4 edges per 256-thread block. Vectorized red.global.add.v4.f32.
// ---------------------------------------------------------------------------
__global__ void __launch_bounds__(256) edge_kernel(
    const int* __restrict__ src, const int* __restrict__ dst,
    const int* __restrict__ rel, const float* __restrict__ comp,
    float* __restrict__ out)
{
    const int e    = blockIdx.x * 4 + (threadIdx.x >> 6);
    const int lane = threadIdx.x & 63;
    if (e >= N_EDGES) return;

    const int s = src[e];
    const int d = dst[e];
    const int r = rel[e];
    const float c0 = __ldg(comp + r * NBASES + 0);
    const float c1 = __ldg(comp + r * NBASES + 1);
    const float c2 = __ldg(comp + r * NBASES + 2);

    const float4* tp = (const float4*)(g_t + (size_t)s * TCOLS);
    float4 v0 = __ldg(tp + lane);
    float4 v1 = __ldg(tp + 64 + lane);
    float4 v2 = __ldg(tp + 128 + lane);

    float4 m;
    m.x = fmaf(c0, v0.x, fmaf(c1, v1.x, c2 * v2.x));
    m.y = fmaf(c0, v0.y, fmaf(c1, v1.y, c2 * v2.y));
    m.z = fmaf(c0, v0.z, fmaf(c1, v1.z, c2 * v2.z));
    m.w = fmaf(c0, v0.w, fmaf(c1, v1.w, c2 * v2.w));

    float* addr = out + (size_t)d * OUT_F + lane * 4;
    asm volatile("red.global.add.v4.f32 [%0], {%1, %2, %3, %4};"
                 :: "l"(addr), "f"(m.x), "f"(m.y), "f"(m.z), "f"(m.w)
                 : "memory");
}

// ---------------------------------------------------------------------------
// ReLU epilogue
// ---------------------------------------------------------------------------
__global__ void relu_kernel(float* __restrict__ out)
{
    int i = blockIdx.x * blockDim.x + threadIdx.x;
    if (i >= N_NODES * OUT_F / 4) return;
    float4 v = ((float4*)out)[i];
    v.x = fmaxf(v.x, 0.0f);
    v.y = fmaxf(v.y, 0.0f);
    v.z = fmaxf(v.z, 0.0f);
    v.w = fmaxf(v.w, 0.0f);
    ((float4*)out)[i] = v;
}

// ---------------------------------------------------------------------------
// Launch
// ---------------------------------------------------------------------------
extern "C" void kernel_launch(void* const* d_in, const int* in_sizes, int n_in,
                              void* d_out, int out_size)
{
    const float* text  = (const float*)d_in[0];   // [64,512,256]
    const int*   src   = (const int*)  d_in[1];   // [E]
    const int*   dst   = (const int*)  d_in[2];   // [E]
    const int*   rel   = (const int*)  d_in[3];   // [E]
    const float* bases = (const float*)d_in[4];   // [3,256,256]
    const float* comp  = (const float*)d_in[5];   // [40,3]
    const float* bias  = (const float*)d_in[6];   // [256]
    float* out = (float*)d_out;                   // [64,512,256]

    const int vec_elems = N_NODES * OUT_F / 4;    // 2,097,152 float4s

    // 1. out = bias (accumulator init)
    init_out_kernel<<<(vec_elems + 255) / 256, 256>>>(out, bias);

    // 2. t = text @ bases (fused over 3 bases, 768 output cols)
    gemm_bases_kernel<<<dim3(TCOLS / BN, N_NODES / BM), 256>>>(text, bases);

    // 3. per-edge combine + scatter-add
    edge_kernel<<<N_EDGES / 4, 256>>>(src, dst, rel, comp, out);

    // 4. ReLU
    relu_kernel<<<(vec_elems + 255) / 256, 256>>>(out);
}

// round 3
// speedup vs baseline: 1.6674x; 1.6674x over previous
#include <cuda_runtime.h>
#include <cuda_fp16.h>
#include <cstdint>

// Problem constants (fixed shapes from reference)
#define N_NODES 32768      // B*S = 64*512
#define IN_F    256
#define OUT_F   256
#define NBASES  3
#define N_EDGES 262144
#define TCOLS   768        // NBASES * OUT_F

// Scratch
__device__ float g_t[(size_t)N_NODES * TCOLS];            // t = h @ bases, 96MB
__device__ __half g_Ah[(size_t)N_NODES * IN_F];           // fp16 hi of text
__device__ __half g_Al[(size_t)N_NODES * IN_F];           // fp16 lo of text
__device__ __half g_Bh[(size_t)NBASES * IN_F * OUT_F];    // fp16 hi of bases [b][k][n]
__device__ __half g_Bl[(size_t)NBASES * IN_F * OUT_F];    // fp16 lo of bases

__device__ __forceinline__ uint32_t smem_u32(const void* p) {
    uint32_t a;
    asm("{ .reg .u64 t; cvta.to.shared.u64 t, %1; cvt.u32.u64 %0, t; }" : "=r"(a) : "l"(p));
    return a;
}

// ---------------------------------------------------------------------------
// Split prep: v -> (hi = rn16(v), lo = rn16(v - hi)); combined ~2^-24 accurate
// ---------------------------------------------------------------------------
__global__ void split_kernel(const float* __restrict__ src,
                             __half* __restrict__ dh, __half* __restrict__ dl, int n4)
{
    int i = blockIdx.x * blockDim.x + threadIdx.x;
    if (i >= n4) return;
    float4 v = ((const float4*)src)[i];
    __half hx = __float2half_rn(v.x), hy = __float2half_rn(v.y);
    __half hz = __float2half_rn(v.z), hw = __float2half_rn(v.w);
    __half lx = __float2half_rn(v.x - __half2float(hx));
    __half ly = __float2half_rn(v.y - __half2float(hy));
    __half lz = __float2half_rn(v.z - __half2float(hz));
    __half lw = __float2half_rn(v.w - __half2float(hw));
    ((__half2*)dh)[2 * i + 0] = __halves2half2(hx, hy);
    ((__half2*)dh)[2 * i + 1] = __halves2half2(hz, hw);
    ((__half2*)dl)[2 * i + 0] = __halves2half2(lx, ly);
    ((__half2*)dl)[2 * i + 1] = __halves2half2(lz, lw);
}

// ---------------------------------------------------------------------------
// Tensor-core GEMM (legacy mma.sync path; tcgen05 is rejected by this bench's
// compute_103 PTX stage). C[m, n] = A[m,:] . B[:,n], n = b*256+o.
// 3-term fp16 compensation: Ah*Bh + Al*Bh + Ah*Bl.
// CTA: 128x128, K chunked by 64, 2-stage cp.async double buffer.
// 8 warps as 4(M) x 2(N): warp tile 32x64, mma.m16n8k16.
// ---------------------------------------------------------------------------
#define SAROW 144u                 // 64+8 halfs padded -> conflict-free ldmatrix
#define SBROW 272u                 // 128+8 halfs padded
#define OFF_AL 18432u              // 128*144
#define OFF_BH 36864u
#define OFF_BL (36864u + 17408u)   // B tile = 64*272
#define STAGE_B 71680u             // per-stage bytes
#define GEMM_SMEM (2 * 71680)

__device__ __forceinline__ void ldm_x4(uint32_t* r, uint32_t addr) {
    asm volatile("ldmatrix.sync.aligned.m8n8.x4.shared.b16 {%0,%1,%2,%3}, [%4];"
                 : "=r"(r[0]), "=r"(r[1]), "=r"(r[2]), "=r"(r[3]) : "r"(addr));
}
__device__ __forceinline__ void ldm_x4t(uint32_t* r, uint32_t addr) {
    asm volatile("ldmatrix.sync.aligned.m8n8.x4.trans.shared.b16 {%0,%1,%2,%3}, [%4];"
                 : "=r"(r[0]), "=r"(r[1]), "=r"(r[2]), "=r"(r[3]) : "r"(addr));
}
__device__ __forceinline__ void mma16816(float* c, const uint32_t* a, const uint32_t* b) {
    asm volatile("mma.sync.aligned.m16n8k16.row.col.f32.f16.f16.f32 "
                 "{%0,%1,%2,%3}, {%4,%5,%6,%7}, {%8,%9}, {%0,%1,%2,%3};"
                 : "+f"(c[0]), "+f"(c[1]), "+f"(c[2]), "+f"(c[3])
                 : "r"(a[0]), "r"(a[1]), "r"(a[2]), "r"(a[3]), "r"(b[0]), "r"(b[1]));
}
__device__ __forceinline__ void cpa16(uint32_t dst, const void* src) {
    asm volatile("cp.async.cg.shared.global [%0], [%1], 16;" :: "r"(dst), "l"(src) : "memory");
}

__device__ __forceinline__ void gemm_load_chunk(uint32_t sb, int s, int m0, int n0, int c, int tid)
{
    const uint32_t so = sb + (uint32_t)s * STAGE_B;
    const int k0 = c << 6;
    const int b  = n0 >> 8;              // basis for this N tile (128 | 256)
    const int nc = n0 & 255;
    // A tiles: 128 rows x 64 halfs (8 x 16B chunks per row)
    #pragma unroll
    for (int i = 0; i < 4; i++) {
        int idx = tid + (i << 8);
        int row = idx >> 3, ch = idx & 7;
        const __half* sh = g_Ah + (size_t)(m0 + row) * IN_F + k0 + (ch << 3);
        const __half* sl = g_Al + (size_t)(m0 + row) * IN_F + k0 + (ch << 3);
        uint32_t d = so + (uint32_t)row * SAROW + (uint32_t)(ch << 4);
        cpa16(d, sh);
        cpa16(d + OFF_AL, sl);
    }
    // B tiles: 64 rows x 128 halfs (16 x 16B chunks per row)
    #pragma unroll
    for (int i = 0; i < 4; i++) {
        int idx = tid + (i << 8);
        int row = idx >> 4, ch = idx & 15;
        size_t goff = (size_t)b * (IN_F * OUT_F) + (size_t)(k0 + row) * OUT_F + nc + (ch << 3);
        uint32_t d = so + (uint32_t)row * SBROW + (uint32_t)(ch << 4);
        cpa16(d + OFF_BH, g_Bh + goff);
        cpa16(d + OFF_BL, g_Bl + goff);
    }
    asm volatile("cp.async.commit_group;" ::: "memory");
}

__global__ void __launch_bounds__(256, 1) gemm_tc_kernel()
{
    extern __shared__ char smem[];
    const uint32_t sb = smem_u32(smem);
    const int tid  = threadIdx.x;
    const int wid  = tid >> 5;
    const int lane = tid & 31;
    const int wm = wid >> 1;          // 0..3 (M)
    const int wn = wid & 1;           // 0..1 (N)
    const int n0 = blockIdx.x << 7;
    const int m0 = blockIdx.y << 7;

    // Per-lane ldmatrix address components
    const uint32_t a_lane = (uint32_t)((lane & 15) * SAROW + (lane >> 4) * 16) + (uint32_t)(wm * 32) * SAROW;
    const uint32_t b_lane = (uint32_t)((lane & 15) * SBROW + (lane >> 4) * 16) + (uint32_t)(wn * 128);

    float acc[2][8][4];
    #pragma unroll
    for (int mt = 0; mt < 2; mt++)
        #pragma unroll
        for (int nt = 0; nt < 8; nt++)
            #pragma unroll
            for (int q = 0; q < 4; q++) acc[mt][nt][q] = 0.0f;

    gemm_load_chunk(sb, 0, m0, n0, 0, tid);

    for (int c = 0; c < 4; c++) {
        if (c + 1 < 4) {
            gemm_load_chunk(sb, (c + 1) & 1, m0, n0, c + 1, tid);
            asm volatile("cp.async.wait_group 1;" ::: "memory");
        } else {
            asm volatile("cp.async.wait_group 0;" ::: "memory");
        }
        __syncthreads();

        const uint32_t so = sb + (uint32_t)(c & 1) * STAGE_B;
        #pragma unroll
        for (int kk = 0; kk < 4; kk++) {
            uint32_t ah[2][4], al[2][4];
            #pragma unroll
            for (int mt = 0; mt < 2; mt++) {
                uint32_t aa = so + a_lane + (uint32_t)(mt * 16) * SAROW + (uint32_t)(kk * 32);
                ldm_x4(ah[mt], aa);
                ldm_x4(al[mt], aa + OFF_AL);
            }
            #pragma unroll
            for (int p = 0; p < 4; p++) {
                uint32_t bh[4], bl[4];
                uint32_t ba = so + b_lane + (uint32_t)(kk * 16) * SBROW + (uint32_t)(p * 32);
                ldm_x4t(bh, ba + OFF_BH);
                ldm_x4t(bl, ba + OFF_BL);
                #pragma unroll
                for (int s = 0; s < 2; s++) {
                    const int nt = p * 2 + s;
                    #pragma unroll
                    for (int mt = 0; mt < 2; mt++) {
                        mma16816(acc[mt][nt], ah[mt], bh + 2 * s);
                        mma16816(acc[mt][nt], al[mt], bh + 2 * s);
                        mma16816(acc[mt][nt], ah[mt], bl + 2 * s);
                    }
                }
            }
        }
        __syncthreads();
    }

    // Epilogue: write C tile to g_t
    #pragma unroll
    for (int mt = 0; mt < 2; mt++) {
        int row0 = m0 + wm * 32 + mt * 16 + (lane >> 2);
        #pragma unroll
        for (int nt = 0; nt < 8; nt++) {
            int col = n0 + wn * 64 + nt * 8 + (lane & 3) * 2;
            float* p0 = g_t + (size_t)row0 * TCOLS + col;
            float* p1 = p0 + 8 * TCOLS;
            p0[0] = acc[mt][nt][0]; p0[1] = acc[mt][nt][1];
            p1[0] = acc[mt][nt][2]; p1[1] = acc[mt][nt][3];
        }
    }
}

// ---------------------------------------------------------------------------
// Init output with bias (accumulator init; d_out poisoned to 0xAA)
// ---------------------------------------------------------------------------
__global__ void init_out_kernel(float* __restrict__ out, const float* __restrict__ bias)
{
    int i = blockIdx.x * blockDim.x + threadIdx.x;
    if (i >= N_NODES * OUT_F / 4) return;
    float4 bv = *(const float4*)(bias + ((i & 63) << 2));
    ((float4*)out)[i] = bv;
}

// ---------------------------------------------------------------------------
// Edge kernel: msg_e = sum_b comp[rel_e,b] * t[src_e, b, :], scatter-add to
// out[dst_e]. 64 threads per edge, vectorized red.global.add.v4.f32.
// ---------------------------------------------------------------------------
__global__ void __launch_bounds__(256) edge_kernel(
    const int* __restrict__ src, const int* __restrict__ dst,
    const int* __restrict__ rel, const float* __restrict__ comp,
    float* __restrict__ out)
{
    const int e    = blockIdx.x * 4 + (threadIdx.x >> 6);
    const int lane = threadIdx.x & 63;
    if (e >= N_EDGES) return;

    const int s = src[e];
    const int d = dst[e];
    const int r = rel[e];
    const float c0 = __ldg(comp + r * NBASES + 0);
    const float c1 = __ldg(comp + r * NBASES + 1);
    const float c2 = __ldg(comp + r * NBASES + 2);

    const float4* tp = (const float4*)(g_t + (size_t)s * TCOLS);
    float4 v0 = __ldg(tp + lane);
    float4 v1 = __ldg(tp + 64 + lane);
    float4 v2 = __ldg(tp + 128 + lane);

    float4 m;
    m.x = fmaf(c0, v0.x, fmaf(c1, v1.x, c2 * v2.x));
    m.y = fmaf(c0, v0.y, fmaf(c1, v1.y, c2 * v2.y));
    m.z = fmaf(c0, v0.z, fmaf(c1, v1.z, c2 * v2.z));
    m.w = fmaf(c0, v0.w, fmaf(c1, v1.w, c2 * v2.w));

    float* addr = out + (size_t)d * OUT_F + lane * 4;
    asm volatile("red.global.add.v4.f32 [%0], {%1, %2, %3, %4};"
                 :: "l"(addr), "f"(m.x), "f"(m.y), "f"(m.z), "f"(m.w)
                 : "memory");
}

// ---------------------------------------------------------------------------
// ReLU epilogue
// ---------------------------------------------------------------------------
__global__ void relu_kernel(float* __restrict__ out)
{
    int i = blockIdx.x * blockDim.x + threadIdx.x;
    if (i >= N_NODES * OUT_F / 4) return;
    float4 v = ((float4*)out)[i];
    v.x = fmaxf(v.x, 0.0f);
    v.y = fmaxf(v.y, 0.0f);
    v.z = fmaxf(v.z, 0.0f);
    v.w = fmaxf(v.w, 0.0f);
    ((float4*)out)[i] = v;
}

// ---------------------------------------------------------------------------
// Launch
// ---------------------------------------------------------------------------
extern "C" void kernel_launch(void* const* d_in, const int* in_sizes, int n_in,
                              void* d_out, int out_size)
{
    const float* text  = (const float*)d_in[0];   // [64,512,256]
    const int*   src   = (const int*)  d_in[1];   // [E]
    const int*   dst   = (const int*)  d_in[2];   // [E]
    const int*   rel   = (const int*)  d_in[3];   // [E]
    const float* bases = (const float*)d_in[4];   // [3,256,256]
    const float* comp  = (const float*)d_in[5];   // [40,3]
    const float* bias  = (const float*)d_in[6];   // [256]
    float* out = (float*)d_out;                   // [64,512,256]

    cudaFuncSetAttribute(gemm_tc_kernel, cudaFuncAttributeMaxDynamicSharedMemorySize, GEMM_SMEM);

    const int vec_elems = N_NODES * OUT_F / 4;

    // 1. out = bias (accumulator init)
    init_out_kernel<<<(vec_elems + 255) / 256, 256>>>(out, bias);

    // 2. fp16 hi/lo splits of A and B
    __half *ah, *al, *bh, *bl;
    cudaGetSymbolAddress((void**)&ah, g_Ah);
    cudaGetSymbolAddress((void**)&al, g_Al);
    cudaGetSymbolAddress((void**)&bh, g_Bh);
    cudaGetSymbolAddress((void**)&bl, g_Bl);
    split_kernel<<<(N_NODES * IN_F / 4 + 255) / 256, 256>>>(text, ah, al, N_NODES * IN_F / 4);
    split_kernel<<<(NBASES * IN_F * OUT_F / 4 + 255) / 256, 256>>>(bases, bh, bl, NBASES * IN_F * OUT_F / 4);

    // 3. t = text @ bases on the tensor pipe (3-term fp16 compensation)
    gemm_tc_kernel<<<dim3(TCOLS / 128, N_NODES / 128), 256, GEMM_SMEM>>>();

    // 4. per-edge combine + scatter-add
    edge_kernel<<<N_EDGES / 4, 256>>>(src, dst, rel, comp, out);

    // 5. ReLU
    relu_kernel<<<(vec_elems + 255) / 256, 256>>>(out);
}

// round 4
// speedup vs baseline: 2.0311x; 1.2181x over previous
#include <cuda_runtime.h>
#include <cuda_fp16.h>
#include <cstdint>

// Problem constants (fixed shapes from reference)
#define N_NODES 32768      // B*S = 64*512
#define IN_F    256
#define OUT_F   256
#define NBASES  3
#define N_EDGES 262144
#define TCOLS   768        // NBASES * OUT_F

// Scratch
__device__ float g_t[(size_t)N_NODES * TCOLS];            // t = h @ bases, 96MB
__device__ __half g_Ah[(size_t)N_NODES * IN_F];           // fp16 hi of text
__device__ __half g_Al[(size_t)N_NODES * IN_F];           // fp16 lo of text
__device__ __half g_Bh[(size_t)NBASES * IN_F * OUT_F];    // fp16 hi of bases [b][k][n]

__device__ __forceinline__ uint32_t smem_u32(const void* p) {
    uint32_t a;
    asm("{ .reg .u64 t; cvta.to.shared.u64 t, %1; cvt.u32.u64 %0, t; }" : "=r"(a) : "l"(p));
    return a;
}

// ---------------------------------------------------------------------------
// Splits: A -> (hi, lo) fp16 pair; B -> hi only (Ah*Bl term dropped: its
// contribution is ~1.4e-4 norm-relative, threshold is 1e-3)
// ---------------------------------------------------------------------------
__global__ void split_hl_kernel(const float* __restrict__ src,
                                __half* __restrict__ dh, __half* __restrict__ dl, int n4)
{
    int i = blockIdx.x * blockDim.x + threadIdx.x;
    if (i >= n4) return;
    float4 v = ((const float4*)src)[i];
    __half hx = __float2half_rn(v.x), hy = __float2half_rn(v.y);
    __half hz = __float2half_rn(v.z), hw = __float2half_rn(v.w);
    __half lx = __float2half_rn(v.x - __half2float(hx));
    __half ly = __float2half_rn(v.y - __half2float(hy));
    __half lz = __float2half_rn(v.z - __half2float(hz));
    __half lw = __float2half_rn(v.w - __half2float(hw));
    ((__half2*)dh)[2 * i + 0] = __halves2half2(hx, hy);
    ((__half2*)dh)[2 * i + 1] = __halves2half2(hz, hw);
    ((__half2*)dl)[2 * i + 0] = __halves2half2(lx, ly);
    ((__half2*)dl)[2 * i + 1] = __halves2half2(lz, lw);
}

__global__ void split_h_kernel(const float* __restrict__ src, __half* __restrict__ dh, int n4)
{
    int i = blockIdx.x * blockDim.x + threadIdx.x;
    if (i >= n4) return;
    float4 v = ((const float4*)src)[i];
    ((__half2*)dh)[2 * i + 0] = __halves2half2(__float2half_rn(v.x), __float2half_rn(v.y));
    ((__half2*)dh)[2 * i + 1] = __halves2half2(__float2half_rn(v.z), __float2half_rn(v.w));
}

// ---------------------------------------------------------------------------
// Tensor-core GEMM (legacy mma.sync; tcgen05 rejected by compute_103 stage).
// C[m, n] = A[m,:] . B[:,n], n = b*256+o.  2-term: Ah*Bh + Al*Bh.
// CTA: 128x128, K chunked by 64, 2-stage cp.async, 2 CTAs/SM.
// 8 warps as 4(M) x 2(N): warp tile 32x64, mma.m16n8k16.
// ---------------------------------------------------------------------------
#define SAROW 144u                 // 64 halfs + 16B pad (bytes per A row)
#define SBROW 272u                 // 128 halfs + 16B pad (bytes per B row)
#define OFF_AL 18432u              // 128*144
#define OFF_BH 36864u
#define STAGE_B 54272u             // Ah 18432 | Al 18432 | Bh 17408
#define GEMM_SMEM (2 * 54272)

__device__ __forceinline__ void ldm_x4(uint32_t* r, uint32_t addr) {
    asm volatile("ldmatrix.sync.aligned.m8n8.x4.shared.b16 {%0,%1,%2,%3}, [%4];"
                 : "=r"(r[0]), "=r"(r[1]), "=r"(r[2]), "=r"(r[3]) : "r"(addr));
}
__device__ __forceinline__ void ldm_x4t(uint32_t* r, uint32_t addr) {
    asm volatile("ldmatrix.sync.aligned.m8n8.x4.trans.shared.b16 {%0,%1,%2,%3}, [%4];"
                 : "=r"(r[0]), "=r"(r[1]), "=r"(r[2]), "=r"(r[3]) : "r"(addr));
}
__device__ __forceinline__ void mma16816(float* c, const uint32_t* a, const uint32_t* b) {
    asm volatile("mma.sync.aligned.m16n8k16.row.col.f32.f16.f16.f32 "
                 "{%0,%1,%2,%3}, {%4,%5,%6,%7}, {%8,%9}, {%0,%1,%2,%3};"
                 : "+f"(c[0]), "+f"(c[1]), "+f"(c[2]), "+f"(c[3])
                 : "r"(a[0]), "r"(a[1]), "r"(a[2]), "r"(a[3]), "r"(b[0]), "r"(b[1]));
}
__device__ __forceinline__ void cpa16(uint32_t dst, const void* src) {
    asm volatile("cp.async.cg.shared.global [%0], [%1], 16;" :: "r"(dst), "l"(src) : "memory");
}

__device__ __forceinline__ void gemm_load_chunk(uint32_t sb, int s, int m0, int n0, int c, int tid)
{
    const uint32_t so = sb + (uint32_t)s * STAGE_B;
    const int k0 = c << 6;
    const int b  = n0 >> 8;
    const int nc = n0 & 255;
    // A tiles: 128 rows x 64 halfs (8 x 16B per row), hi + lo
    #pragma unroll
    for (int i = 0; i < 4; i++) {
        int idx = tid + (i << 8);
        int row = idx >> 3, ch = idx & 7;
        size_t goff = (size_t)(m0 + row) * IN_F + k0 + (ch << 3);
        uint32_t d = so + (uint32_t)row * SAROW + (uint32_t)(ch << 4);
        cpa16(d, g_Ah + goff);
        cpa16(d + OFF_AL, g_Al + goff);
    }
    // B tile: 64 rows x 128 halfs (16 x 16B per row), hi only
    #pragma unroll
    for (int i = 0; i < 4; i++) {
        int idx = tid + (i << 8);
        int row = idx >> 4, ch = idx & 15;
        size_t goff = (size_t)b * (IN_F * OUT_F) + (size_t)(k0 + row) * OUT_F + nc + (ch << 3);
        cpa16(so + OFF_BH + (uint32_t)row * SBROW + (uint32_t)(ch << 4), g_Bh + goff);
    }
    asm volatile("cp.async.commit_group;" ::: "memory");
}

__global__ void __launch_bounds__(256, 2) gemm_tc_kernel()
{
    extern __shared__ char smem[];
    const uint32_t sb = smem_u32(smem);
    const int tid  = threadIdx.x;
    const int wid  = tid >> 5;
    const int lane = tid & 31;
    const int wm = wid >> 1;          // 0..3 (M)
    const int wn = wid & 1;           // 0..1 (N)
    const int n0 = blockIdx.x << 7;
    const int m0 = blockIdx.y << 7;

    const uint32_t a_lane = (uint32_t)((lane & 15) * SAROW + (lane >> 4) * 16) + (uint32_t)(wm * 32) * SAROW;
    const uint32_t b_lane = (uint32_t)((lane & 15) * SBROW + (lane >> 4) * 16) + (uint32_t)(wn * 128);

    float acc[2][8][4];
    #pragma unroll
    for (int mt = 0; mt < 2; mt++)
        #pragma unroll
        for (int nt = 0; nt < 8; nt++)
            #pragma unroll
            for (int q = 0; q < 4; q++) acc[mt][nt][q] = 0.0f;

    gemm_load_chunk(sb, 0, m0, n0, 0, tid);

    for (int c = 0; c < 4; c++) {
        if (c + 1 < 4) {
            gemm_load_chunk(sb, (c + 1) & 1, m0, n0, c + 1, tid);
            asm volatile("cp.async.wait_group 1;" ::: "memory");
        } else {
            asm volatile("cp.async.wait_group 0;" ::: "memory");
        }
        __syncthreads();

        const uint32_t so = sb + (uint32_t)(c & 1) * STAGE_B;
        #pragma unroll
        for (int kk = 0; kk < 4; kk++) {
            uint32_t ah[2][4], al[2][4];
            #pragma unroll
            for (int mt = 0; mt < 2; mt++) {
                uint32_t aa = so + a_lane + (uint32_t)(mt * 16) * SAROW + (uint32_t)(kk * 32);
                ldm_x4(ah[mt], aa);
                ldm_x4(al[mt], aa + OFF_AL);
            }
            #pragma unroll
            for (int p = 0; p < 4; p++) {
                uint32_t bh[4];
                ldm_x4t(bh, so + OFF_BH + b_lane + (uint32_t)(kk * 16) * SBROW + (uint32_t)(p * 32));
                #pragma unroll
                for (int s = 0; s < 2; s++) {
                    const int nt = p * 2 + s;
                    #pragma unroll
                    for (int mt = 0; mt < 2; mt++) {
                        mma16816(acc[mt][nt], ah[mt], bh + 2 * s);
                        mma16816(acc[mt][nt], al[mt], bh + 2 * s);
                    }
                }
            }
        }
        __syncthreads();
    }

    // Epilogue: write C tile to g_t
    #pragma unroll
    for (int mt = 0; mt < 2; mt++) {
        int row0 = m0 + wm * 32 + mt * 16 + (lane >> 2);
        #pragma unroll
        for (int nt = 0; nt < 8; nt++) {
            int col = n0 + wn * 64 + nt * 8 + (lane & 3) * 2;
            float* p0 = g_t + (size_t)row0 * TCOLS + col;
            float* p1 = p0 + 8 * TCOLS;
            p0[0] = acc[mt][nt][0]; p0[1] = acc[mt][nt][1];
            p1[0] = acc[mt][nt][2]; p1[1] = acc[mt][nt][3];
        }
    }
}

// ---------------------------------------------------------------------------
// Init output with bias (accumulator init; d_out poisoned to 0xAA)
// ---------------------------------------------------------------------------
__global__ void init_out_kernel(float* __restrict__ out, const float* __restrict__ bias)
{
    int i = blockIdx.x * blockDim.x + threadIdx.x;
    if (i >= N_NODES * OUT_F / 4) return;
    float4 bv = *(const float4*)(bias + ((i & 63) << 2));
    ((float4*)out)[i] = bv;
}

// ---------------------------------------------------------------------------
// Edge kernel: msg_e = sum_b comp[rel_e,b] * t[src_e, b, :], scatter-add to
// out[dst_e]. 64 threads per edge, vectorized red.global.add.v4.f32.
// ---------------------------------------------------------------------------
__global__ void __launch_bounds__(256) edge_kernel(
    const int* __restrict__ src, const int* __restrict__ dst,
    const int* __restrict__ rel, const float* __restrict__ comp,
    float* __restrict__ out)
{
    const int e    = blockIdx.x * 4 + (threadIdx.x >> 6);
    const int lane = threadIdx.x & 63;
    if (e >= N_EDGES) return;

    const int s = src[e];
    const int d = dst[e];
    const int r = rel[e];
    const float c0 = __ldg(comp + r * NBASES + 0);
    const float c1 = __ldg(comp + r * NBASES + 1);
    const float c2 = __ldg(comp + r * NBASES + 2);

    const float4* tp = (const float4*)(g_t + (size_t)s * TCOLS);
    float4 v0 = __ldg(tp + lane);
    float4 v1 = __ldg(tp + 64 + lane);
    float4 v2 = __ldg(tp + 128 + lane);

    float4 m;
    m.x = fmaf(c0, v0.x, fmaf(c1, v1.x, c2 * v2.x));
    m.y = fmaf(c0, v0.y, fmaf(c1, v1.y, c2 * v2.y));
    m.z = fmaf(c0, v0.z, fmaf(c1, v1.z, c2 * v2.z));
    m.w = fmaf(c0, v0.w, fmaf(c1, v1.w, c2 * v2.w));

    float* addr = out + (size_t)d * OUT_F + lane * 4;
    asm volatile("red.global.add.v4.f32 [%0], {%1, %2, %3, %4};"
                 :: "l"(addr), "f"(m.x), "f"(m.y), "f"(m.z), "f"(m.w)
                 : "memory");
}

// ---------------------------------------------------------------------------
// ReLU epilogue
// ---------------------------------------------------------------------------
__global__ void relu_kernel(float* __restrict__ out)
{
    int i = blockIdx.x * blockDim.x + threadIdx.x;
    if (i >= N_NODES * OUT_F / 4) return;
    float4 v = ((float4*)out)[i];
    v.x = fmaxf(v.x, 0.0f);
    v.y = fmaxf(v.y, 0.0f);
    v.z = fmaxf(v.z, 0.0f);
    v.w = fmaxf(v.w, 0.0f);
    ((float4*)out)[i] = v;
}

// ---------------------------------------------------------------------------
// Launch
// ---------------------------------------------------------------------------
extern "C" void kernel_launch(void* const* d_in, const int* in_sizes, int n_in,
                              void* d_out, int out_size)
{
    const float* text  = (const float*)d_in[0];   // [64,512,256]
    const int*   src   = (const int*)  d_in[1];   // [E]
    const int*   dst   = (const int*)  d_in[2];   // [E]
    const int*   rel   = (const int*)  d_in[3];   // [E]
    const float* bases = (const float*)d_in[4];   // [3,256,256]
    const float* comp  = (const float*)d_in[5];   // [40,3]
    const float* bias  = (const float*)d_in[6];   // [256]
    float* out = (float*)d_out;                   // [64,512,256]

    cudaFuncSetAttribute(gemm_tc_kernel, cudaFuncAttributeMaxDynamicSharedMemorySize, GEMM_SMEM);

    const int vec_elems = N_NODES * OUT_F / 4;

    // 1. out = bias (accumulator init)
    init_out_kernel<<<(vec_elems + 255) / 256, 256>>>(out, bias);

    // 2. fp16 splits: A -> hi/lo, B -> hi
    __half *ah, *al, *bh;
    cudaGetSymbolAddress((void**)&ah, g_Ah);
    cudaGetSymbolAddress((void**)&al, g_Al);
    cudaGetSymbolAddress((void**)&bh, g_Bh);
    split_hl_kernel<<<(N_NODES * IN_F / 4 + 255) / 256, 256>>>(text, ah, al, N_NODES * IN_F / 4);
    split_h_kernel<<<(NBASES * IN_F * OUT_F / 4 + 255) / 256, 256>>>(bases, bh, NBASES * IN_F * OUT_F / 4);

    // 3. t = text @ bases on the tensor pipe (2-term fp16 compensation)
    gemm_tc_kernel<<<dim3(TCOLS / 128, N_NODES / 128), 256, GEMM_SMEM>>>();

    // 4. per-edge combine + scatter-add
    edge_kernel<<<N_EDGES / 4, 256>>>(src, dst, rel, comp, out);

    // 5. ReLU
    relu_kernel<<<(vec_elems + 255) / 256, 256>>>(out);
}

// round 5
// speedup vs baseline: 2.3174x; 1.1409x over previous
#include <cuda_runtime.h>
#include <cuda_fp16.h>
#include <cstdint>

// Problem constants (fixed shapes from reference)
#define N_NODES 32768      // B*S = 64*512
#define IN_F    256
#define OUT_F   256
#define NBASES  3
#define N_EDGES 262144
#define TCOLS   768        // NBASES * OUT_F

// Scratch
__device__ __half g_t[(size_t)N_NODES * TCOLS];           // t = h @ bases (fp16), 48MB
__device__ __half g_Ah[(size_t)N_NODES * IN_F];           // fp16 hi of text
__device__ __half g_Al[(size_t)N_NODES * IN_F];           // fp16 lo of text
__device__ __half g_Bh[(size_t)NBASES * IN_F * OUT_F];    // fp16 hi of bases [b][k][n]

__device__ __forceinline__ uint32_t smem_u32(const void* p) {
    uint32_t a;
    asm("{ .reg .u64 t; cvta.to.shared.u64 t, %1; cvt.u32.u64 %0, t; }" : "=r"(a) : "l"(p));
    return a;
}

// ---------------------------------------------------------------------------
// Splits: A -> (hi, lo) fp16 pair; B -> hi only
// ---------------------------------------------------------------------------
__global__ void split_hl_kernel(const float* __restrict__ src,
                                __half* __restrict__ dh, __half* __restrict__ dl, int n4)
{
    int i = blockIdx.x * blockDim.x + threadIdx.x;
    if (i >= n4) return;
    float4 v = ((const float4*)src)[i];
    __half hx = __float2half_rn(v.x), hy = __float2half_rn(v.y);
    __half hz = __float2half_rn(v.z), hw = __float2half_rn(v.w);
    __half lx = __float2half_rn(v.x - __half2float(hx));
    __half ly = __float2half_rn(v.y - __half2float(hy));
    __half lz = __float2half_rn(v.z - __half2float(hz));
    __half lw = __float2half_rn(v.w - __half2float(hw));
    ((__half2*)dh)[2 * i + 0] = __halves2half2(hx, hy);
    ((__half2*)dh)[2 * i + 1] = __halves2half2(hz, hw);
    ((__half2*)dl)[2 * i + 0] = __halves2half2(lx, ly);
    ((__half2*)dl)[2 * i + 1] = __halves2half2(lz, lw);
}

__global__ void split_h_kernel(const float* __restrict__ src, __half* __restrict__ dh, int n4)
{
    int i = blockIdx.x * blockDim.x + threadIdx.x;
    if (i >= n4) return;
    float4 v = ((const float4*)src)[i];
    ((__half2*)dh)[2 * i + 0] = __halves2half2(__float2half_rn(v.x), __float2half_rn(v.y));
    ((__half2*)dh)[2 * i + 1] = __halves2half2(__float2half_rn(v.z), __float2half_rn(v.w));
}

// ---------------------------------------------------------------------------
// Tensor-core GEMM (legacy mma.sync; tcgen05 rejected by compute_103 stage).
// C[m, n] = A[m,:] . B[:,n], n = b*256+o.  2-term: Ah*Bh + Al*Bh.
// CTA: 128x64, K chunked by 32 (8 chunks), 2-stage cp.async, 3 CTAs/SM.
// 8 warps as 4(M) x 2(N): warp tile 32x32, mma.m16n8k16.
// ---------------------------------------------------------------------------
#define SAROW 80u                  // 32 halfs + 16B pad (5*16B: conflict-free ldsm)
#define SBROW 144u                 // 64 halfs + 16B pad (9*16B)
#define OFF_AL 10240u              // 128*80
#define OFF_B  20480u
#define STAGE_B 25088u             // Ah 10240 | Al 10240 | B 4608
#define GEMM_SMEM (2 * 25088)

__device__ __forceinline__ void ldm_x4(uint32_t* r, uint32_t addr) {
    asm volatile("ldmatrix.sync.aligned.m8n8.x4.shared.b16 {%0,%1,%2,%3}, [%4];"
                 : "=r"(r[0]), "=r"(r[1]), "=r"(r[2]), "=r"(r[3]) : "r"(addr));
}
__device__ __forceinline__ void ldm_x4t(uint32_t* r, uint32_t addr) {
    asm volatile("ldmatrix.sync.aligned.m8n8.x4.trans.shared.b16 {%0,%1,%2,%3}, [%4];"
                 : "=r"(r[0]), "=r"(r[1]), "=r"(r[2]), "=r"(r[3]) : "r"(addr));
}
__device__ __forceinline__ void mma16816(float* c, const uint32_t* a, const uint32_t* b) {
    asm volatile("mma.sync.aligned.m16n8k16.row.col.f32.f16.f16.f32 "
                 "{%0,%1,%2,%3}, {%4,%5,%6,%7}, {%8,%9}, {%0,%1,%2,%3};"
                 : "+f"(c[0]), "+f"(c[1]), "+f"(c[2]), "+f"(c[3])
                 : "r"(a[0]), "r"(a[1]), "r"(a[2]), "r"(a[3]), "r"(b[0]), "r"(b[1]));
}
__device__ __forceinline__ void cpa16(uint32_t dst, const void* src) {
    asm volatile("cp.async.cg.shared.global [%0], [%1], 16;" :: "r"(dst), "l"(src) : "memory");
}

__device__ __forceinline__ void gemm_load_chunk(uint32_t sb, int s, int m0, int n0, int c, int tid)
{
    const uint32_t so = sb + (uint32_t)s * STAGE_B;
    const int k0 = c << 5;
    const int b  = n0 >> 8;              // basis index (n0 multiple of 64)
    const int nc = n0 & 255;
    // A: 128 rows x 32 halfs (4 x 16B per row), hi + lo
    #pragma unroll
    for (int i = 0; i < 2; i++) {
        int idx = tid + (i << 8);
        int row = idx >> 2, ch = idx & 3;
        size_t goff = (size_t)(m0 + row) * IN_F + k0 + (ch << 3);
        uint32_t d = so + (uint32_t)row * SAROW + (uint32_t)(ch << 4);
        cpa16(d, g_Ah + goff);
        cpa16(d + OFF_AL, g_Al + goff);
    }
    // B: 32 rows x 64 halfs (8 x 16B per row), hi only
    {
        int row = tid >> 3, ch = tid & 7;
        size_t goff = (size_t)b * (IN_F * OUT_F) + (size_t)(k0 + row) * OUT_F + nc + (ch << 3);
        cpa16(so + OFF_B + (uint32_t)row * SBROW + (uint32_t)(ch << 4), g_Bh + goff);
    }
    asm volatile("cp.async.commit_group;" ::: "memory");
}

__global__ void __launch_bounds__(256, 3) gemm_tc_kernel()
{
    extern __shared__ char smem[];
    const uint32_t sb = smem_u32(smem);
    const int tid  = threadIdx.x;
    const int wid  = tid >> 5;
    const int lane = tid & 31;
    const int wm = wid >> 1;          // 0..3 (M)
    const int wn = wid & 1;           // 0..1 (N)
    const int n0 = blockIdx.x << 6;
    const int m0 = blockIdx.y << 7;

    const uint32_t a_lane = (uint32_t)((lane & 15) * SAROW + (lane >> 4) * 16) + (uint32_t)(wm * 32) * SAROW;
    const uint32_t b_lane = (uint32_t)((lane & 15) * SBROW + (lane >> 4) * 16) + (uint32_t)(wn * 64);

    float acc[2][4][4];
    #pragma unroll
    for (int mt = 0; mt < 2; mt++)
        #pragma unroll
        for (int nt = 0; nt < 4; nt++)
            #pragma unroll
            for (int q = 0; q < 4; q++) acc[mt][nt][q] = 0.0f;

    gemm_load_chunk(sb, 0, m0, n0, 0, tid);

    for (int c = 0; c < 8; c++) {
        if (c + 1 < 8) {
            gemm_load_chunk(sb, (c + 1) & 1, m0, n0, c + 1, tid);
            asm volatile("cp.async.wait_group 1;" ::: "memory");
        } else {
            asm volatile("cp.async.wait_group 0;" ::: "memory");
        }
        __syncthreads();

        const uint32_t so = sb + (uint32_t)(c & 1) * STAGE_B;
        #pragma unroll
        for (int kk = 0; kk < 2; kk++) {
            uint32_t ah[2][4], al[2][4];
            #pragma unroll
            for (int mt = 0; mt < 2; mt++) {
                uint32_t aa = so + a_lane + (uint32_t)(mt * 16) * SAROW + (uint32_t)(kk * 32);
                ldm_x4(ah[mt], aa);
                ldm_x4(al[mt], aa + OFF_AL);
            }
            #pragma unroll
            for (int p = 0; p < 2; p++) {
                uint32_t bh[4];
                ldm_x4t(bh, so + OFF_B + b_lane + (uint32_t)(kk * 16) * SBROW + (uint32_t)(p * 32));
                #pragma unroll
                for (int s = 0; s < 2; s++) {
                    const int nt = p * 2 + s;
                    #pragma unroll
                    for (int mt = 0; mt < 2; mt++) {
                        mma16816(acc[mt][nt], ah[mt], bh + 2 * s);
                        mma16816(acc[mt][nt], al[mt], bh + 2 * s);
                    }
                }
            }
        }
        __syncthreads();
    }

    // Epilogue: write C tile to g_t as fp16
    #pragma unroll
    for (int mt = 0; mt < 2; mt++) {
        int row0 = m0 + wm * 32 + mt * 16 + (lane >> 2);
        #pragma unroll
        for (int nt = 0; nt < 4; nt++) {
            int col = n0 + wn * 32 + nt * 8 + (lane & 3) * 2;
            __half* p0 = g_t + (size_t)row0 * TCOLS + col;
            __half* p1 = p0 + 8 * TCOLS;
            *(__half2*)p0 = __floats2half2_rn(acc[mt][nt][0], acc[mt][nt][1]);
            *(__half2*)p1 = __floats2half2_rn(acc[mt][nt][2], acc[mt][nt][3]);
        }
    }
}

// ---------------------------------------------------------------------------
// Init output with bias (accumulator init; d_out poisoned to 0xAA)
// ---------------------------------------------------------------------------
__global__ void init_out_kernel(float* __restrict__ out, const float* __restrict__ bias)
{
    int i = blockIdx.x * blockDim.x + threadIdx.x;
    if (i >= N_NODES * OUT_F / 4) return;
    float4 bv = *(const float4*)(bias + ((i & 63) << 2));
    ((float4*)out)[i] = bv;
}

// ---------------------------------------------------------------------------
// Edge kernel: msg_e = sum_b comp[rel_e,b] * t[src_e, b, :], scatter-add to
// out[dst_e]. 64 threads per edge; t is fp16 (half L2 traffic), RED v4 fp32.
// ---------------------------------------------------------------------------
__global__ void __launch_bounds__(256) edge_kernel(
    const int* __restrict__ src, const int* __restrict__ dst,
    const int* __restrict__ rel, const float* __restrict__ comp,
    float* __restrict__ out)
{
    const int e    = blockIdx.x * 4 + (threadIdx.x >> 6);
    const int lane = threadIdx.x & 63;
    if (e >= N_EDGES) return;

    const int s = src[e];
    const int d = dst[e];
    const int r = rel[e];
    const float c0 = __ldg(comp + r * NBASES + 0);
    const float c1 = __ldg(comp + r * NBASES + 1);
    const float c2 = __ldg(comp + r * NBASES + 2);

    const uint2* tp = (const uint2*)(g_t + (size_t)s * TCOLS);   // 4 halfs per uint2
    uint2 u0 = __ldg(tp + lane);          // basis 0, cols 4*lane..4*lane+3
    uint2 u1 = __ldg(tp + 64 + lane);     // basis 1
    uint2 u2 = __ldg(tp + 128 + lane);    // basis 2

    float2 p00 = __half22float2(*(__half2*)&u0.x), p01 = __half22float2(*(__half2*)&u0.y);
    float2 p10 = __half22float2(*(__half2*)&u1.x), p11 = __half22float2(*(__half2*)&u1.y);
    float2 p20 = __half22float2(*(__half2*)&u2.x), p21 = __half22float2(*(__half2*)&u2.y);

    float4 m;
    m.x = fmaf(c0, p00.x, fmaf(c1, p10.x, c2 * p20.x));
    m.y = fmaf(c0, p00.y, fmaf(c1, p10.y, c2 * p20.y));
    m.z = fmaf(c0, p01.x, fmaf(c1, p11.x, c2 * p21.x));
    m.w = fmaf(c0, p01.y, fmaf(c1, p11.y, c2 * p21.y));

    float* addr = out + (size_t)d * OUT_F + lane * 4;
    asm volatile("red.global.add.v4.f32 [%0], {%1, %2, %3, %4};"
                 :: "l"(addr), "f"(m.x), "f"(m.y), "f"(m.z), "f"(m.w)
                 : "memory");
}

// ---------------------------------------------------------------------------
// ReLU epilogue
// ---------------------------------------------------------------------------
__global__ void relu_kernel(float* __restrict__ out)
{
    int i = blockIdx.x * blockDim.x + threadIdx.x;
    if (i >= N_NODES * OUT_F / 4) return;
    float4 v = ((float4*)out)[i];
    v.x = fmaxf(v.x, 0.0f);
    v.y = fmaxf(v.y, 0.0f);
    v.z = fmaxf(v.z, 0.0f);
    v.w = fmaxf(v.w, 0.0f);
    ((float4*)out)[i] = v;
}

// ---------------------------------------------------------------------------
// Launch
// ---------------------------------------------------------------------------
extern "C" void kernel_launch(void* const* d_in, const int* in_sizes, int n_in,
                              void* d_out, int out_size)
{
    const float* text  = (const float*)d_in[0];   // [64,512,256]
    const int*   src   = (const int*)  d_in[1];   // [E]
    const int*   dst   = (const int*)  d_in[2];   // [E]
    const int*   rel   = (const int*)  d_in[3];   // [E]
    const float* bases = (const float*)d_in[4];   // [3,256,256]
    const float* comp  = (const float*)d_in[5];   // [40,3]
    const float* bias  = (const float*)d_in[6];   // [256]
    float* out = (float*)d_out;                   // [64,512,256]

    cudaFuncSetAttribute(gemm_tc_kernel, cudaFuncAttributeMaxDynamicSharedMemorySize, GEMM_SMEM);

    const int vec_elems = N_NODES * OUT_F / 4;

    // 1. out = bias (accumulator init)
    init_out_kernel<<<(vec_elems + 255) / 256, 256>>>(out, bias);

    // 2. fp16 splits: A -> hi/lo, B -> hi
    __half *ah, *al, *bh;
    cudaGetSymbolAddress((void**)&ah, g_Ah);
    cudaGetSymbolAddress((void**)&al, g_Al);
    cudaGetSymbolAddress((void**)&bh, g_Bh);
    split_hl_kernel<<<(N_NODES * IN_F / 4 + 255) / 256, 256>>>(text, ah, al, N_NODES * IN_F / 4);
    split_h_kernel<<<(NBASES * IN_F * OUT_F / 4 + 255) / 256, 256>>>(bases, bh, NBASES * IN_F * OUT_F / 4);

    // 3. t = text @ bases on the tensor pipe (2-term fp16 compensation)
    gemm_tc_kernel<<<dim3(TCOLS / 64, N_NODES / 128), 256, GEMM_SMEM>>>();

    // 4. per-edge combine + scatter-add
    edge_kernel<<<N_EDGES / 4, 256>>>(src, dst, rel, comp, out);

    // 5. ReLU
    relu_kernel<<<(vec_elems + 255) / 256, 256>>>(out);
}

// round 6
// speedup vs baseline: 2.7678x; 1.1944x over previous
#include <cuda_runtime.h>
#include <cuda_fp16.h>
#include <cstdint>

// Problem constants (fixed shapes from reference)
#define N_NODES 32768      // B*S = 64*512
#define IN_F    256
#define OUT_F   256
#define NBASES  3
#define N_EDGES 262144
#define TCOLS   768        // NBASES * OUT_F

// Scratch
__device__ __half g_t[(size_t)N_NODES * TCOLS];           // t = h @ bases (fp16), 48MB
__device__ __half g_Ah[(size_t)N_NODES * IN_F];           // fp16 text
__device__ __half g_Bh[(size_t)NBASES * IN_F * OUT_F];    // fp16 bases [b][k][n]

__device__ __forceinline__ uint32_t smem_u32(const void* p) {
    uint32_t a;
    asm("{ .reg .u64 t; cvta.to.shared.u64 t, %1; cvt.u32.u64 %0, t; }" : "=r"(a) : "l"(p));
    return a;
}

// ---------------------------------------------------------------------------
// fp16 convert (hi only; single-term GEMM — HMMA pipe is rt-saturated, so
// halving MMA count is the only lever; error budget verified round-over-round)
// ---------------------------------------------------------------------------
__global__ void split_h_kernel(const float* __restrict__ src, __half* __restrict__ dh, int n4)
{
    int i = blockIdx.x * blockDim.x + threadIdx.x;
    if (i >= n4) return;
    float4 v = ((const float4*)src)[i];
    ((__half2*)dh)[2 * i + 0] = __halves2half2(__float2half_rn(v.x), __float2half_rn(v.y));
    ((__half2*)dh)[2 * i + 1] = __halves2half2(__float2half_rn(v.z), __float2half_rn(v.w));
}

// ---------------------------------------------------------------------------
// Tensor-core GEMM (legacy mma.sync; tcgen05 rejected by compute_103 stage).
// C[m, n] = A[m,:] . B[:,n], n = b*256+o.  Single term: Ah*Bh.
// CTA: 128x64, K chunked by 32 (8 chunks), 2-stage cp.async, 3 CTAs/SM.
// 8 warps as 4(M) x 2(N): warp tile 32x32, mma.m16n8k16.
// ---------------------------------------------------------------------------
#define SAROW 80u                  // 32 halfs + 16B pad (5*16B: conflict-free ldsm)
#define SBROW 144u                 // 64 halfs + 16B pad (9*16B)
#define OFF_B  10240u              // 128*80
#define STAGE_B 14848u             // Ah 10240 | B 4608
#define GEMM_SMEM (2 * 14848)

__device__ __forceinline__ void ldm_x4(uint32_t* r, uint32_t addr) {
    asm volatile("ldmatrix.sync.aligned.m8n8.x4.shared.b16 {%0,%1,%2,%3}, [%4];"
                 : "=r"(r[0]), "=r"(r[1]), "=r"(r[2]), "=r"(r[3]) : "r"(addr));
}
__device__ __forceinline__ void ldm_x4t(uint32_t* r, uint32_t addr) {
    asm volatile("ldmatrix.sync.aligned.m8n8.x4.trans.shared.b16 {%0,%1,%2,%3}, [%4];"
                 : "=r"(r[0]), "=r"(r[1]), "=r"(r[2]), "=r"(r[3]) : "r"(addr));
}
__device__ __forceinline__ void mma16816(float* c, const uint32_t* a, const uint32_t* b) {
    asm volatile("mma.sync.aligned.m16n8k16.row.col.f32.f16.f16.f32 "
                 "{%0,%1,%2,%3}, {%4,%5,%6,%7}, {%8,%9}, {%0,%1,%2,%3};"
                 : "+f"(c[0]), "+f"(c[1]), "+f"(c[2]), "+f"(c[3])
                 : "r"(a[0]), "r"(a[1]), "r"(a[2]), "r"(a[3]), "r"(b[0]), "r"(b[1]));
}
__device__ __forceinline__ void cpa16(uint32_t dst, const void* src) {
    asm volatile("cp.async.cg.shared.global [%0], [%1], 16;" :: "r"(dst), "l"(src) : "memory");
}

__device__ __forceinline__ void gemm_load_chunk(uint32_t sb, int s, int m0, int n0, int c, int tid)
{
    const uint32_t so = sb + (uint32_t)s * STAGE_B;
    const int k0 = c << 5;
    const int b  = n0 >> 8;              // basis index (n0 multiple of 64)
    const int nc = n0 & 255;
    // A: 128 rows x 32 halfs (4 x 16B per row)
    #pragma unroll
    for (int i = 0; i < 2; i++) {
        int idx = tid + (i << 8);
        int row = idx >> 2, ch = idx & 3;
        size_t goff = (size_t)(m0 + row) * IN_F + k0 + (ch << 3);
        cpa16(so + (uint32_t)row * SAROW + (uint32_t)(ch << 4), g_Ah + goff);
    }
    // B: 32 rows x 64 halfs (8 x 16B per row)
    {
        int row = tid >> 3, ch = tid & 7;
        size_t goff = (size_t)b * (IN_F * OUT_F) + (size_t)(k0 + row) * OUT_F + nc + (ch << 3);
        cpa16(so + OFF_B + (uint32_t)row * SBROW + (uint32_t)(ch << 4), g_Bh + goff);
    }
    asm volatile("cp.async.commit_group;" ::: "memory");
}

__global__ void __launch_bounds__(256, 3) gemm_tc_kernel()
{
    extern __shared__ char smem[];
    const uint32_t sb = smem_u32(smem);
    const int tid  = threadIdx.x;
    const int wid  = tid >> 5;
    const int lane = tid & 31;
    const int wm = wid >> 1;          // 0..3 (M)
    const int wn = wid & 1;           // 0..1 (N)
    const int n0 = blockIdx.x << 6;
    const int m0 = blockIdx.y << 7;

    const uint32_t a_lane = (uint32_t)((lane & 15) * SAROW + (lane >> 4) * 16) + (uint32_t)(wm * 32) * SAROW;
    const uint32_t b_lane = (uint32_t)((lane & 15) * SBROW + (lane >> 4) * 16) + (uint32_t)(wn * 64);

    float acc[2][4][4];
    #pragma unroll
    for (int mt = 0; mt < 2; mt++)
        #pragma unroll
        for (int nt = 0; nt < 4; nt++)
            #pragma unroll
            for (int q = 0; q < 4; q++) acc[mt][nt][q] = 0.0f;

    gemm_load_chunk(sb, 0, m0, n0, 0, tid);

    for (int c = 0; c < 8; c++) {
        if (c + 1 < 8) {
            gemm_load_chunk(sb, (c + 1) & 1, m0, n0, c + 1, tid);
            asm volatile("cp.async.wait_group 1;" ::: "memory");
        } else {
            asm volatile("cp.async.wait_group 0;" ::: "memory");
        }
        __syncthreads();

        const uint32_t so = sb + (uint32_t)(c & 1) * STAGE_B;
        #pragma unroll
        for (int kk = 0; kk < 2; kk++) {
            uint32_t ah[2][4];
            #pragma unroll
            for (int mt = 0; mt < 2; mt++)
                ldm_x4(ah[mt], so + a_lane + (uint32_t)(mt * 16) * SAROW + (uint32_t)(kk * 32));
            #pragma unroll
            for (int p = 0; p < 2; p++) {
                uint32_t bh[4];
                ldm_x4t(bh, so + OFF_B + b_lane + (uint32_t)(kk * 16) * SBROW + (uint32_t)(p * 32));
                #pragma unroll
                for (int s = 0; s < 2; s++) {
                    const int nt = p * 2 + s;
                    #pragma unroll
                    for (int mt = 0; mt < 2; mt++)
                        mma16816(acc[mt][nt], ah[mt], bh + 2 * s);
                }
            }
        }
        __syncthreads();
    }

    // Epilogue: write C tile to g_t as fp16
    #pragma unroll
    for (int mt = 0; mt < 2; mt++) {
        int row0 = m0 + wm * 32 + mt * 16 + (lane >> 2);
        #pragma unroll
        for (int nt = 0; nt < 4; nt++) {
            int col = n0 + wn * 32 + nt * 8 + (lane & 3) * 2;
            __half* p0 = g_t + (size_t)row0 * TCOLS + col;
            __half* p1 = p0 + 8 * TCOLS;
            *(__half2*)p0 = __floats2half2_rn(acc[mt][nt][0], acc[mt][nt][1]);
            *(__half2*)p1 = __floats2half2_rn(acc[mt][nt][2], acc[mt][nt][3]);
        }
    }
}

// ---------------------------------------------------------------------------
// Init output with bias (accumulator init; d_out poisoned to 0xAA)
// ---------------------------------------------------------------------------
__global__ void init_out_kernel(float* __restrict__ out, const float* __restrict__ bias)
{
    int i = blockIdx.x * blockDim.x + threadIdx.x;
    if (i >= N_NODES * OUT_F / 4) return;
    float4 bv = *(const float4*)(bias + ((i & 63) << 2));
    ((float4*)out)[i] = bv;
}

// ---------------------------------------------------------------------------
// Edge kernel: msg_e = sum_b comp[rel_e,b] * t[src_e, b, :], scatter-add to
// out[dst_e]. 64 threads per edge; t is fp16, RED v4 fp32.
// ---------------------------------------------------------------------------
__global__ void __launch_bounds__(256) edge_kernel(
    const int* __restrict__ src, const int* __restrict__ dst,
    const int* __restrict__ rel, const float* __restrict__ comp,
    float* __restrict__ out)
{
    const int e    = blockIdx.x * 4 + (threadIdx.x >> 6);
    const int lane = threadIdx.x & 63;
    if (e >= N_EDGES) return;

    const int s = src[e];
    const int d = dst[e];
    const int r = rel[e];
    const float c0 = __ldg(comp + r * NBASES + 0);
    const float c1 = __ldg(comp + r * NBASES + 1);
    const float c2 = __ldg(comp + r * NBASES + 2);

    const uint2* tp = (const uint2*)(g_t + (size_t)s * TCOLS);   // 4 halfs per uint2
    uint2 u0 = __ldg(tp + lane);          // basis 0, cols 4*lane..4*lane+3
    uint2 u1 = __ldg(tp + 64 + lane);     // basis 1
    uint2 u2 = __ldg(tp + 128 + lane);    // basis 2

    float2 p00 = __half22float2(*(__half2*)&u0.x), p01 = __half22float2(*(__half2*)&u0.y);
    float2 p10 = __half22float2(*(__half2*)&u1.x), p11 = __half22float2(*(__half2*)&u1.y);
    float2 p20 = __half22float2(*(__half2*)&u2.x), p21 = __half22float2(*(__half2*)&u2.y);

    float4 m;
    m.x = fmaf(c0, p00.x, fmaf(c1, p10.x, c2 * p20.x));
    m.y = fmaf(c0, p00.y, fmaf(c1, p10.y, c2 * p20.y));
    m.z = fmaf(c0, p01.x, fmaf(c1, p11.x, c2 * p21.x));
    m.w = fmaf(c0, p01.y, fmaf(c1, p11.y, c2 * p21.y));

    float* addr = out + (size_t)d * OUT_F + lane * 4;
    asm volatile("red.global.add.v4.f32 [%0], {%1, %2, %3, %4};"
                 :: "l"(addr), "f"(m.x), "f"(m.y), "f"(m.z), "f"(m.w)
                 : "memory");
}

// ---------------------------------------------------------------------------
// ReLU epilogue
// ---------------------------------------------------------------------------
__global__ void relu_kernel(float* __restrict__ out)
{
    int i = blockIdx.x * blockDim.x + threadIdx.x;
    if (i >= N_NODES * OUT_F / 4) return;
    float4 v = ((float4*)out)[i];
    v.x = fmaxf(v.x, 0.0f);
    v.y = fmaxf(v.y, 0.0f);
    v.z = fmaxf(v.z, 0.0f);
    v.w = fmaxf(v.w, 0.0f);
    ((float4*)out)[i] = v;
}

// ---------------------------------------------------------------------------
// Launch
// ---------------------------------------------------------------------------
extern "C" void kernel_launch(void* const* d_in, const int* in_sizes, int n_in,
                              void* d_out, int out_size)
{
    const float* text  = (const float*)d_in[0];   // [64,512,256]
    const int*   src   = (const int*)  d_in[1];   // [E]
    const int*   dst   = (const int*)  d_in[2];   // [E]
    const int*   rel   = (const int*)  d_in[3];   // [E]
    const float* bases = (const float*)d_in[4];   // [3,256,256]
    const float* comp  = (const float*)d_in[5];   // [40,3]
    const float* bias  = (const float*)d_in[6];   // [256]
    float* out = (float*)d_out;                   // [64,512,256]

    cudaFuncSetAttribute(gemm_tc_kernel, cudaFuncAttributeMaxDynamicSharedMemorySize, GEMM_SMEM);

    const int vec_elems = N_NODES * OUT_F / 4;

    // 1. out = bias (accumulator init)
    init_out_kernel<<<(vec_elems + 255) / 256, 256>>>(out, bias);

    // 2. fp16 converts
    __half *ah, *bh;
    cudaGetSymbolAddress((void**)&ah, g_Ah);
    cudaGetSymbolAddress((void**)&bh, g_Bh);
    split_h_kernel<<<(N_NODES * IN_F / 4 + 255) / 256, 256>>>(text, ah, N_NODES * IN_F / 4);
    split_h_kernel<<<(NBASES * IN_F * OUT_F / 4 + 255) / 256, 256>>>(bases, bh, NBASES * IN_F * OUT_F / 4);

    // 3. t = text @ bases on the tensor pipe (single-term fp16)
    gemm_tc_kernel<<<dim3(TCOLS / 64, N_NODES / 128), 256, GEMM_SMEM>>>();

    // 4. per-edge combine + scatter-add
    edge_kernel<<<N_EDGES / 4, 256>>>(src, dst, rel, comp, out);

    // 5. ReLU
    relu_kernel<<<(vec_elems + 255) / 256, 256>>>(out);
}